// round 2
// baseline (speedup 1.0000x reference)
#include <cuda_runtime.h>
#include <math.h>

#define TBL 2048          // number of lerp intervals over act in [0,1]
#define KS2 4
#define NBASIS 8
#define NHID 16

// Device-global table: {F(x_i), F(x_{i+1}) - F(x_i)} for x_i = i/TBL
__device__ float2 g_tbl[TBL];

// Full precise evaluation of the scalar chain after the sigmoid:
//   feats_b = exp(-sum_j (a - basis[b][j])^2)
//   h = tanh(feats @ w1 + b1); out = h @ w2 + b2
__device__ __forceinline__ float eval_F(float a,
                                        const float* __restrict__ basis,
                                        const float* __restrict__ w1,
                                        const float* __restrict__ b1,
                                        const float* __restrict__ w2,
                                        const float* __restrict__ b2) {
    float feats[NBASIS];
#pragma unroll
    for (int b = 0; b < NBASIS; ++b) {
        float s = 0.0f;
#pragma unroll
        for (int j = 0; j < KS2; ++j) {
            float df = a - basis[b * KS2 + j];
            s = fmaf(df, df, s);
        }
        feats[b] = expf(-s);   // GAMMA = 1
    }
    float out = b2[0];
#pragma unroll
    for (int j = 0; j < NHID; ++j) {
        float h = b1[j];
#pragma unroll
        for (int b = 0; b < NBASIS; ++b)
            h = fmaf(feats[b], w1[b * NHID + j], h);
        out = fmaf(tanhf(h), w2[j], out);
    }
    return out;
}

__global__ void build_table_kernel(const float* __restrict__ basis,
                                   const float* __restrict__ w1,
                                   const float* __restrict__ b1,
                                   const float* __restrict__ w2,
                                   const float* __restrict__ b2) {
    int i = blockIdx.x * blockDim.x + threadIdx.x;
    if (i >= TBL) return;
    float x0 = (float)i       * (1.0f / TBL);
    float x1 = (float)(i + 1) * (1.0f / TBL);
    float v0 = eval_F(x0, basis, w1, b1, w2, b2);
    float v1 = eval_F(x1, basis, w1, b1, w2, b2);
    g_tbl[i] = make_float2(v0, v1 - v0);
}

__global__ void __launch_bounds__(256)
hybridconv_main_kernel(const float4* __restrict__ data,
                       const float* __restrict__ conv_w,
                       const float* __restrict__ conv_b,
                       float* __restrict__ out, int n) {
    __shared__ float2 tbl[TBL];   // 16 KB
    for (int i = threadIdx.x; i < TBL; i += blockDim.x)
        tbl[i] = g_tbl[i];

    // conv weights: uniform scalar loads (L1-resident, broadcast)
    const float cw0 = __ldg(conv_w + 0);
    const float cw1 = __ldg(conv_w + 1);
    const float cw2 = __ldg(conv_w + 2);
    const float cw3 = __ldg(conv_w + 3);
    const float cb  = __ldg(conv_b);
    __syncthreads();

    const int stride = gridDim.x * blockDim.x;
#pragma unroll 4
    for (int idx = blockIdx.x * blockDim.x + threadIdx.x; idx < n; idx += stride) {
        float4 d = data[idx];
        float logit = fmaf(d.x, cw0, fmaf(d.y, cw1, fmaf(d.z, cw2, fmaf(d.w, cw3, cb))));
        // sigmoid: 1 / (1 + exp(-x)).  exp(-x)=inf -> a=0; exp(-x)=0 -> a=1 (both handled below)
        float a = __fdividef(1.0f, 1.0f + __expf(-logit));
        float t = a * (float)TBL;
        int   i = min((int)t, TBL - 1);   // a==1.0 exactly -> i=TBL-1, frac=1.0
        float frac = t - (float)i;
        float2 e = tbl[i];
        out[idx] = fmaf(frac, e.y, e.x);
    }
}

extern "C" void kernel_launch(void* const* d_in, const int* in_sizes, int n_in,
                              void* d_out, int out_size) {
    // metadata order: data, conv_w, conv_b, basis, w1, b1, w2, b2
    const float4* data   = (const float4*)d_in[0];
    const float*  conv_w = (const float*)d_in[1];
    const float*  conv_b = (const float*)d_in[2];
    const float*  basis  = (const float*)d_in[3];
    const float*  w1     = (const float*)d_in[4];
    const float*  b1     = (const float*)d_in[5];
    const float*  w2     = (const float*)d_in[6];
    const float*  b2     = (const float*)d_in[7];
    float* out = (float*)d_out;

    const int n = in_sizes[0] / 4;   // N patches (data has N*4 floats)

    build_table_kernel<<<(TBL + 255) / 256, 256>>>(basis, w1, b1, w2, b2);

    const int threads = 256;
    const int blocks  = 148 * 8;     // persistent-style grid-stride, 64 warps/SM
    hybridconv_main_kernel<<<blocks, threads>>>(data, conv_w, conv_b, out, n);
}

// round 4
// speedup vs baseline: 1.1348x; 1.1348x over previous
#include <cuda_runtime.h>
#include <math.h>

#define TBL   4096            // lerp intervals over logit x in [-16, 16]
#define TBLN  (TBL + 1)       // nodes
#define XMIN  (-16.0f)
#define XSCALE 128.0f         // TBL / 32
#define KS2 4
#define NBASIS 8
#define NHID 16

// Table of G(x_i) = F(sigmoid(x_i)), x_i = XMIN + i/XSCALE
__device__ float g_vals[TBLN];

__device__ __forceinline__ float fast_tanh(float h) {
    // 1 - 2/(exp(2h)+1); exact limits at +/-inf via IEEE behavior of __expf
    return 1.0f - __fdividef(2.0f, __expf(2.0f * h) + 1.0f);
}

// G(x) = MLP(RBF(sigmoid(x))) — full evaluation, fast-math (table accuracy ~1e-6 is ample)
__device__ float eval_G(float x,
                        const float* __restrict__ basis,
                        const float* __restrict__ w1,
                        const float* __restrict__ b1,
                        const float* __restrict__ w2,
                        const float* __restrict__ b2) {
    float a = __fdividef(1.0f, 1.0f + __expf(-x));   // sigmoid
    float feats[NBASIS];
#pragma unroll
    for (int b = 0; b < NBASIS; ++b) {
        float s = 0.0f;
#pragma unroll
        for (int j = 0; j < KS2; ++j) {
            float df = a - basis[b * KS2 + j];
            s = fmaf(df, df, s);
        }
        feats[b] = __expf(-s);   // GAMMA = 1
    }
    float out = b2[0];
#pragma unroll
    for (int j = 0; j < NHID; ++j) {
        float h = b1[j];
#pragma unroll
        for (int b = 0; b < NBASIS; ++b)
            h = fmaf(feats[b], w1[b * NHID + j], h);
        out = fmaf(fast_tanh(h), w2[j], out);
    }
    return out;
}

__global__ void __launch_bounds__(256)
build_table_kernel(const float* __restrict__ basis,
                   const float* __restrict__ w1,
                   const float* __restrict__ b1,
                   const float* __restrict__ w2,
                   const float* __restrict__ b2) {
    int i = blockIdx.x * blockDim.x + threadIdx.x;
    if (i >= TBLN) return;
    float x = XMIN + (float)i * (1.0f / XSCALE);
    g_vals[i] = eval_G(x, basis, w1, b1, w2, b2);
}

__global__ void __launch_bounds__(256)
hybridconv_main_kernel(const float4* __restrict__ data,
                       const float* __restrict__ conv_w,
                       const float* __restrict__ conv_b,
                       float* __restrict__ out, int n) {
    __shared__ float sval[TBLN];   // ~16.4 KB
    for (int i = threadIdx.x; i < TBLN; i += blockDim.x)
        sval[i] = g_vals[i];

    const float cw0 = __ldg(conv_w + 0);
    const float cw1 = __ldg(conv_w + 1);
    const float cw2 = __ldg(conv_w + 2);
    const float cw3 = __ldg(conv_w + 3);
    const float cb  = __ldg(conv_b);
    __syncthreads();

    const int stride = gridDim.x * blockDim.x;
#pragma unroll 4
    for (int idx = blockIdx.x * blockDim.x + threadIdx.x; idx < n; idx += stride) {
        float4 d = __ldcs(&data[idx]);
        float x = fmaf(d.x, cw0, fmaf(d.y, cw1, fmaf(d.z, cw2, fmaf(d.w, cw3, cb))));
        // map logit -> table coordinate, clamp to [0, TBL-1]
        float t = fmaf(x, XSCALE, (float)(TBL / 2));
        t = fminf(fmaxf(t, 0.0f), (float)(TBL - 1));
        float f = floorf(t);
        int   i = (int)f;
        float frac = t - f;
        float v0 = sval[i];
        float v1 = sval[i + 1];
        __stcs(&out[idx], fmaf(frac, v1 - v0, v0));
    }
}

extern "C" void kernel_launch(void* const* d_in, const int* in_sizes, int n_in,
                              void* d_out, int out_size) {
    // metadata order: data, conv_w, conv_b, basis, w1, b1, w2, b2
    const float4* data   = (const float4*)d_in[0];
    const float*  conv_w = (const float*)d_in[1];
    const float*  conv_b = (const float*)d_in[2];
    const float*  basis  = (const float*)d_in[3];
    const float*  w1     = (const float*)d_in[4];
    const float*  b1     = (const float*)d_in[5];
    const float*  w2     = (const float*)d_in[6];
    const float*  b2     = (const float*)d_in[7];
    float* out = (float*)d_out;

    const int n = in_sizes[0] / 4;   // N patches

    build_table_kernel<<<(TBLN + 255) / 256, 256>>>(basis, w1, b1, w2, b2);

    const int threads = 256;
    const int blocks  = 148 * 8;     // persistent grid-stride
    hybridconv_main_kernel<<<blocks, threads>>>(data, conv_w, conv_b, out, n);
}

// round 5
// speedup vs baseline: 1.2464x; 1.0984x over previous
#include <cuda_runtime.h>
#include <math.h>

#define TBL   4096            // lerp intervals over logit x in [-16, 16]
#define TBLN  (TBL + 1)       // nodes
#define XMIN  (-16.0f)
#define XSCALE 128.0f         // TBL / 32
#define KS2 4
#define NBASIS 8
#define NHID 16

// Table of G(x_i) = F(sigmoid(x_i)), x_i = XMIN + i/XSCALE
__device__ float g_vals[TBLN];

__device__ __forceinline__ float fast_tanh(float h) {
    return 1.0f - __fdividef(2.0f, __expf(2.0f * h) + 1.0f);
}

__device__ float eval_G(float x,
                        const float* __restrict__ basis,
                        const float* __restrict__ w1,
                        const float* __restrict__ b1,
                        const float* __restrict__ w2,
                        const float* __restrict__ b2) {
    float a = __fdividef(1.0f, 1.0f + __expf(-x));   // sigmoid
    float feats[NBASIS];
#pragma unroll
    for (int b = 0; b < NBASIS; ++b) {
        float s = 0.0f;
#pragma unroll
        for (int j = 0; j < KS2; ++j) {
            float df = a - basis[b * KS2 + j];
            s = fmaf(df, df, s);
        }
        feats[b] = __expf(-s);   // GAMMA = 1
    }
    float out = b2[0];
#pragma unroll
    for (int j = 0; j < NHID; ++j) {
        float h = b1[j];
#pragma unroll
        for (int b = 0; b < NBASIS; ++b)
            h = fmaf(feats[b], w1[b * NHID + j], h);
        out = fmaf(fast_tanh(h), w2[j], out);
    }
    return out;
}

__global__ void __launch_bounds__(256)
build_table_kernel(const float* __restrict__ basis,
                   const float* __restrict__ w1,
                   const float* __restrict__ b1,
                   const float* __restrict__ w2,
                   const float* __restrict__ b2) {
    int i = blockIdx.x * blockDim.x + threadIdx.x;
    if (i >= TBLN) return;
    float x = XMIN + (float)i * (1.0f / XSCALE);
    g_vals[i] = eval_G(x, basis, w1, b1, w2, b2);
}

__device__ __forceinline__ float table_lookup(const float* sval, float x) {
    float t = fmaf(x, XSCALE, (float)(TBL / 2));
    t = fminf(fmaxf(t, 0.0f), (float)(TBL - 1));
    float f = floorf(t);
    int   i = (int)f;
    float frac = t - f;
    float v0 = sval[i];
    float v1 = sval[i + 1];
    return fmaf(frac, v1 - v0, v0);
}

__global__ void __launch_bounds__(256, 6)
hybridconv_main_kernel(const float4* __restrict__ data,
                       const float* __restrict__ conv_w,
                       const float* __restrict__ conv_b,
                       float4* __restrict__ out4, int n4) {
    __shared__ float sval[TBLN];   // ~16.4 KB

    // conv weights are harness inputs — independent of the build kernel,
    // safe to load before the PDL dependency resolves.
    const float cw0 = __ldg(conv_w + 0);
    const float cw1 = __ldg(conv_w + 1);
    const float cw2 = __ldg(conv_w + 2);
    const float cw3 = __ldg(conv_w + 3);
    const float cb  = __ldg(conv_b);

    // PDL: block until the build kernel (our upstream dependency) completes.
#if __CUDA_ARCH__ >= 900
    cudaGridDependencySynchronize();
#endif
    for (int i = threadIdx.x; i < TBLN; i += blockDim.x)
        sval[i] = g_vals[i];
    __syncthreads();

    const int stride = gridDim.x * blockDim.x;
    for (int i = blockIdx.x * blockDim.x + threadIdx.x; i < n4; i += stride) {
        const float4* p = data + 4 * i;
        float4 d0 = __ldcs(p + 0);
        float4 d1 = __ldcs(p + 1);
        float4 d2 = __ldcs(p + 2);
        float4 d3 = __ldcs(p + 3);
        float x0 = fmaf(d0.x, cw0, fmaf(d0.y, cw1, fmaf(d0.z, cw2, fmaf(d0.w, cw3, cb))));
        float x1 = fmaf(d1.x, cw0, fmaf(d1.y, cw1, fmaf(d1.z, cw2, fmaf(d1.w, cw3, cb))));
        float x2 = fmaf(d2.x, cw0, fmaf(d2.y, cw1, fmaf(d2.z, cw2, fmaf(d2.w, cw3, cb))));
        float x3 = fmaf(d3.x, cw0, fmaf(d3.y, cw1, fmaf(d3.z, cw2, fmaf(d3.w, cw3, cb))));
        float4 r;
        r.x = table_lookup(sval, x0);
        r.y = table_lookup(sval, x1);
        r.z = table_lookup(sval, x2);
        r.w = table_lookup(sval, x3);
        __stcs(&out4[i], r);
    }
}

extern "C" void kernel_launch(void* const* d_in, const int* in_sizes, int n_in,
                              void* d_out, int out_size) {
    // metadata order: data, conv_w, conv_b, basis, w1, b1, w2, b2
    const float4* data   = (const float4*)d_in[0];
    const float*  conv_w = (const float*)d_in[1];
    const float*  conv_b = (const float*)d_in[2];
    const float*  basis  = (const float*)d_in[3];
    const float*  w1     = (const float*)d_in[4];
    const float*  b1     = (const float*)d_in[5];
    const float*  w2     = (const float*)d_in[6];
    const float*  b2     = (const float*)d_in[7];
    float4* out4 = (float4*)d_out;

    const int n  = in_sizes[0] / 4;   // N patches
    const int n4 = n / 4;             // float4-output groups (N divisible by 4)

    build_table_kernel<<<(TBLN + 255) / 256, 256>>>(basis, w1, b1, w2, b2);

    // Main kernel with programmatic stream serialization: launch overlaps the
    // build kernel; device-side cudaGridDependencySynchronize() provides the
    // actual data dependency on g_vals.
    cudaLaunchConfig_t cfg = {};
    cfg.gridDim  = dim3(148 * 6, 1, 1);
    cfg.blockDim = dim3(256, 1, 1);
    cfg.dynamicSmemBytes = 0;
    cudaLaunchAttribute attr[1];
    attr[0].id = cudaLaunchAttributeProgrammaticStreamSerialization;
    attr[0].val.programmaticStreamSerializationAllowed = 1;
    cfg.attrs = attr;
    cfg.numAttrs = 1;
    cudaLaunchKernelEx(&cfg, hybridconv_main_kernel, data, conv_w, conv_b, out4, n4);
}

// round 7
// speedup vs baseline: 1.2560x; 1.0077x over previous
#include <cuda_runtime.h>
#include <math.h>

#define TBL   2048            // lerp intervals over logit x in [-16, 16]
#define XMIN  (-16.0f)
#define XSCALE 64.0f          // TBL / 32
#define KS2 4
#define NBASIS 8
#define NHID 16

// Table: {G(x_i), G(x_{i+1}) - G(x_i)}, x_i = XMIN + i/XSCALE
__device__ float2 g_tbl[TBL];

__device__ __forceinline__ float fast_tanh(float h) {
    return 1.0f - __fdividef(2.0f, __expf(2.0f * h) + 1.0f);
}

__device__ float eval_G(float x,
                        const float* __restrict__ basis,
                        const float* __restrict__ w1,
                        const float* __restrict__ b1,
                        const float* __restrict__ w2,
                        const float* __restrict__ b2) {
    float a = __fdividef(1.0f, 1.0f + __expf(-x));   // sigmoid
    float feats[NBASIS];
#pragma unroll
    for (int b = 0; b < NBASIS; ++b) {
        float s = 0.0f;
#pragma unroll
        for (int j = 0; j < KS2; ++j) {
            float df = a - basis[b * KS2 + j];
            s = fmaf(df, df, s);
        }
        feats[b] = __expf(-s);   // GAMMA = 1
    }
    float out = b2[0];
#pragma unroll
    for (int j = 0; j < NHID; ++j) {
        float h = b1[j];
#pragma unroll
        for (int b = 0; b < NBASIS; ++b)
            h = fmaf(feats[b], w1[b * NHID + j], h);
        out = fmaf(fast_tanh(h), w2[j], out);
    }
    return out;
}

__global__ void __launch_bounds__(256)
build_table_kernel(const float* __restrict__ basis,
                   const float* __restrict__ w1,
                   const float* __restrict__ b1,
                   const float* __restrict__ w2,
                   const float* __restrict__ b2) {
    int i = blockIdx.x * blockDim.x + threadIdx.x;
    if (i >= TBL) return;
    float x0 = XMIN + (float)i       * (1.0f / XSCALE);
    float x1 = XMIN + (float)(i + 1) * (1.0f / XSCALE);
    float v0 = eval_G(x0, basis, w1, b1, w2, b2);
    float v1 = eval_G(x1, basis, w1, b1, w2, b2);
    g_tbl[i] = make_float2(v0, v1 - v0);
}

__device__ __forceinline__ float table_lookup(const float2* tbl, float x) {
    float t = fmaf(x, XSCALE, (float)(TBL / 2));
    t = fminf(fmaxf(t, 0.0f), (float)(TBL - 1));
    float f = floorf(t);
    int   i = (int)f;
    float frac = t - f;
    float2 e = tbl[i];                // single LDS.64
    return fmaf(frac, e.y, e.x);
}

__global__ void __launch_bounds__(256)
hybridconv_main_kernel(const float4* __restrict__ data,
                       const float* __restrict__ conv_w,
                       const float* __restrict__ conv_b,
                       float4* __restrict__ out4, int n4) {
    __shared__ float2 tbl[TBL];   // 16 KB -> 8 blocks/SM, 64 warps

    const float cw0 = __ldg(conv_w + 0);
    const float cw1 = __ldg(conv_w + 1);
    const float cw2 = __ldg(conv_w + 2);
    const float cw3 = __ldg(conv_w + 3);
    const float cb  = __ldg(conv_b);

#if __CUDA_ARCH__ >= 900
    cudaGridDependencySynchronize();   // PDL: wait for build kernel
#endif
    for (int i = threadIdx.x; i < TBL; i += blockDim.x)
        tbl[i] = g_tbl[i];
    __syncthreads();

    const int stride = gridDim.x * blockDim.x;
#pragma unroll 2
    for (int i = blockIdx.x * blockDim.x + threadIdx.x; i < n4; i += stride) {
        const float4* p = data + 4 * i;
        float4 d0 = __ldcs(p + 0);
        float4 d1 = __ldcs(p + 1);
        float4 d2 = __ldcs(p + 2);
        float4 d3 = __ldcs(p + 3);
        float x0 = fmaf(d0.x, cw0, fmaf(d0.y, cw1, fmaf(d0.z, cw2, fmaf(d0.w, cw3, cb))));
        float x1 = fmaf(d1.x, cw0, fmaf(d1.y, cw1, fmaf(d1.z, cw2, fmaf(d1.w, cw3, cb))));
        float x2 = fmaf(d2.x, cw0, fmaf(d2.y, cw1, fmaf(d2.z, cw2, fmaf(d2.w, cw3, cb))));
        float x3 = fmaf(d3.x, cw0, fmaf(d3.y, cw1, fmaf(d3.z, cw2, fmaf(d3.w, cw3, cb))));
        float4 r;
        r.x = table_lookup(tbl, x0);
        r.y = table_lookup(tbl, x1);
        r.z = table_lookup(tbl, x2);
        r.w = table_lookup(tbl, x3);
        __stcs(&out4[i], r);
    }
}

extern "C" void kernel_launch(void* const* d_in, const int* in_sizes, int n_in,
                              void* d_out, int out_size) {
    // metadata order: data, conv_w, conv_b, basis, w1, b1, w2, b2
    const float4* data   = (const float4*)d_in[0];
    const float*  conv_w = (const float*)d_in[1];
    const float*  conv_b = (const float*)d_in[2];
    const float*  basis  = (const float*)d_in[3];
    const float*  w1     = (const float*)d_in[4];
    const float*  b1     = (const float*)d_in[5];
    const float*  w2     = (const float*)d_in[6];
    const float*  b2     = (const float*)d_in[7];
    float4* out4 = (float4*)d_out;

    const int n  = in_sizes[0] / 4;   // N patches
    const int n4 = n / 4;             // float4 output groups

    build_table_kernel<<<(TBL + 255) / 256, 256>>>(basis, w1, b1, w2, b2);

    cudaLaunchConfig_t cfg = {};
    cfg.gridDim  = dim3(148 * 8, 1, 1);
    cfg.blockDim = dim3(256, 1, 1);
    cfg.dynamicSmemBytes = 0;
    cudaLaunchAttribute attr[1];
    attr[0].id = cudaLaunchAttributeProgrammaticStreamSerialization;
    attr[0].val.programmaticStreamSerializationAllowed = 1;
    cfg.attrs = attr;
    cfg.numAttrs = 1;
    cudaLaunchKernelEx(&cfg, hybridconv_main_kernel, data, conv_w, conv_b, out4, n4);
}